// round 3
// baseline (speedup 1.0000x reference)
#include <cuda_runtime.h>
#include <math.h>

// Problem constants
#define BB 256
#define TT 1000
#define NN 200
#define NII 7
#define HK 100              // K-range per half-thread
#define NTHREADS 416        // 13 warps: 208 pairs (200 neurons + z + 7 dummy)

#define ALPHA_F 0.2f
#define OMA_F   0.8f
#define NSC_F   0.0948683292f   // 0.15*sqrt(2*0.2)

// packed fp32x2 FMA: acc.lo += w.lo*ylo ; acc.hi += w.hi*yhi
__device__ __forceinline__ void ffma2(unsigned long long& acc, unsigned long long w,
                                      float ylo, float yhi) {
    asm("{\n\t"
        ".reg .b64 yy;\n\t"
        "mov.b64 yy, {%2, %3};\n\t"
        "fma.rn.f32x2 %0, %1, yy, %0;\n\t"
        "}"
        : "+l"(acc) : "l"(w), "f"(ylo), "f"(yhi));
}

__device__ __forceinline__ float hsum2(unsigned long long a) {
    float2 f;
    asm("mov.b64 {%0, %1}, %2;" : "=f"(f.x), "=f"(f.y) : "l"(a));
    return f.x + f.y;
}

__global__ void __launch_bounds__(NTHREADS, 1)
rnn_persistent_kernel(const float* __restrict__ y0,
                      const float* __restrict__ u_seq,
                      const float* __restrict__ noise,
                      const float* __restrict__ W_in_raw,
                      const float* __restrict__ W_rec,
                      const float* __restrict__ b_rec,
                      const float* __restrict__ w_out,
                      const float* __restrict__ b_out,
                      float* __restrict__ out)
{
    __shared__ __align__(16) float y_s[2][2][NN];   // [buf][row][neuron]
    __shared__ float u_s[2][2][NII];                // [buf][row][input]

    const int tid = threadIdx.x;
    const int h   = tid & 1;           // K-half (lane pair)
    const int n   = tid >> 1;          // 0..207
    const int nc  = (n < NN) ? n : NN; // clamp: extras use w_out row (valid mem)
    const bool is_neuron = (n <  NN);
    const bool is_z      = (n == NN);
    const bool h0        = (h == 0);
    const int  b0 = blockIdx.x * 2;
    const int  b1 = b0 + 1;
    const int  koff = h * HK;

    float* __restrict__ y_seq = out;
    float* __restrict__ z_seq = out + (size_t)BB * TT * NN;
    float* __restrict__ y_fin = out + (size_t)BB * TT * NN + (size_t)BB * TT;

    // ---- register-resident HALF weight row (100 fp32 = 50 x b64) ----
    unsigned long long w[HK / 2];
    {
        const float* base = (nc == NN) ? (w_out + koff)
                                       : (W_rec + (size_t)nc * NN + koff);
        const unsigned long long* wp = reinterpret_cast<const unsigned long long*>(base);
        #pragma unroll
        for (int m = 0; m < HK / 2; ++m) w[m] = __ldg(&wp[m]);
    }

    float wia[NII];
    float brec = 0.f, bout = 0.f;
    float yold0 = 0.f, yold1 = 0.f, nz0 = 0.f, nz1 = 0.f;
    if (h0 && is_neuron) {
        #pragma unroll
        for (int i = 0; i < NII; ++i) wia[i] = fabsf(W_in_raw[n * NII + i]);
        brec  = b_rec[n];
        yold0 = y0[(size_t)b0 * NN + n];
        yold1 = y0[(size_t)b1 * NN + n];
        y_s[0][0][n] = yold0;
        y_s[0][1][n] = yold1;
        nz0 = noise[(size_t)b0 * TT * NN + n];
        nz1 = noise[(size_t)b1 * TT * NN + n];
    }
    if (is_z) bout = b_out[0];
    if (tid < 2 * NII) {
        int bl = tid / NII, i = tid % NII;
        u_s[0][bl][i] = u_seq[(size_t)(b0 + bl) * TT * NII + i];
    }
    __syncthreads();

    int buf = 0;
    for (int t = 0; t < TT; ++t) {
        // ---- prefetch next step's noise / u ----
        float nz0n = 0.f, nz1n = 0.f, un = 0.f;
        if (h0 && is_neuron && (t + 1 < TT)) {
            nz0n = __ldcs(&noise[((size_t)b0 * TT + (t + 1)) * NN + n]);
            nz1n = __ldcs(&noise[((size_t)b1 * TT + (t + 1)) * NN + n]);
        }
        if (tid < 2 * NII && (t + 1 < TT)) {
            int bl = tid / NII, i = tid % NII;
            un = __ldcs(&u_seq[((size_t)(b0 + bl) * TT + (t + 1)) * NII + i]);
        }

        // ---- half-dot over k in [koff, koff+100): 4 independent FFMA2 chains
        const float4* Y0 = reinterpret_cast<const float4*>(y_s[buf][0] + koff);
        const float4* Y1 = reinterpret_cast<const float4*>(y_s[buf][1] + koff);
        unsigned long long c0a = 0ull, c0b = 0ull, c1a = 0ull, c1b = 0ull;
        #pragma unroll
        for (int m = 0; m < HK / 4; ++m) {
            float4 p = Y0[m];
            float4 q = Y1[m];
            ffma2(c0a, w[2 * m],     p.x, p.y);
            ffma2(c0b, w[2 * m + 1], p.z, p.w);
            ffma2(c1a, w[2 * m],     q.x, q.y);
            ffma2(c1b, w[2 * m + 1], q.z, q.w);
        }
        float pre0 = hsum2(c0a) + hsum2(c0b);
        float pre1 = hsum2(c1a) + hsum2(c1b);
        // combine halves within the lane pair — no barrier, no SMEM
        pre0 += __shfl_xor_sync(0xFFFFFFFFu, pre0, 1);
        pre1 += __shfl_xor_sync(0xFFFFFFFFu, pre1, 1);

        if (h0 && is_neuron) {
            float dr0 = brec, dr1 = brec;
            #pragma unroll
            for (int i = 0; i < NII; ++i) {
                dr0 = fmaf(wia[i], u_s[buf][0][i], dr0);
                dr1 = fmaf(wia[i], u_s[buf][1][i], dr1);
            }
            float r0 = fmaxf(pre0 + dr0, 0.f);
            float r1 = fmaxf(pre1 + dr1, 0.f);
            float yn0 = fmaf(OMA_F, yold0, fmaf(ALPHA_F, r0, NSC_F * nz0));
            float yn1 = fmaf(OMA_F, yold1, fmaf(ALPHA_F, r1, NSC_F * nz1));
            y_s[buf ^ 1][0][n] = yn0;
            y_s[buf ^ 1][1][n] = yn1;
            __stcs(&y_seq[((size_t)b0 * TT + t) * NN + n], yn0);
            __stcs(&y_seq[((size_t)b1 * TT + t) * NN + n], yn1);
            yold0 = yn0; yold1 = yn1;
            nz0 = nz0n; nz1 = nz1n;
        } else if (h0 && is_z && t >= 1) {
            // dot was over y_{t-1}
            z_seq[(size_t)b0 * TT + (t - 1)] = 1.f / (1.f + expf(-(pre0 + bout)));
            z_seq[(size_t)b1 * TT + (t - 1)] = 1.f / (1.f + expf(-(pre1 + bout)));
        }
        if (tid < 2 * NII && (t + 1 < TT)) {
            int bl = tid / NII, i = tid % NII;
            u_s[buf ^ 1][bl][i] = un;
        }
        __syncthreads();
        buf ^= 1;
    }

    // ---- tails ----
    if (h0 && is_neuron) {
        y_fin[(size_t)b0 * NN + n] = yold0;
        y_fin[(size_t)b1 * NN + n] = yold1;
    }
    // final z over y_{T-1} (now in y_s[buf]); all threads execute (shfl safety)
    {
        const float4* Y0 = reinterpret_cast<const float4*>(y_s[buf][0] + koff);
        const float4* Y1 = reinterpret_cast<const float4*>(y_s[buf][1] + koff);
        unsigned long long c0a = 0ull, c0b = 0ull, c1a = 0ull, c1b = 0ull;
        #pragma unroll
        for (int m = 0; m < HK / 4; ++m) {
            float4 p = Y0[m];
            float4 q = Y1[m];
            ffma2(c0a, w[2 * m],     p.x, p.y);
            ffma2(c0b, w[2 * m + 1], p.z, p.w);
            ffma2(c1a, w[2 * m],     q.x, q.y);
            ffma2(c1b, w[2 * m + 1], q.z, q.w);
        }
        float pre0 = hsum2(c0a) + hsum2(c0b);
        float pre1 = hsum2(c1a) + hsum2(c1b);
        pre0 += __shfl_xor_sync(0xFFFFFFFFu, pre0, 1);
        pre1 += __shfl_xor_sync(0xFFFFFFFFu, pre1, 1);
        if (h0 && is_z) {
            z_seq[(size_t)b0 * TT + (TT - 1)] = 1.f / (1.f + expf(-(pre0 + bout)));
            z_seq[(size_t)b1 * TT + (TT - 1)] = 1.f / (1.f + expf(-(pre1 + bout)));
        }
    }
}

extern "C" void kernel_launch(void* const* d_in, const int* in_sizes, int n_in,
                              void* d_out, int out_size) {
    const float* y0       = (const float*)d_in[0];
    const float* u_seq    = (const float*)d_in[1];
    const float* noise    = (const float*)d_in[2];
    const float* W_in_raw = (const float*)d_in[3];
    const float* W_rec    = (const float*)d_in[4];
    const float* b_rec    = (const float*)d_in[5];
    const float* w_out    = (const float*)d_in[6];
    const float* b_out    = (const float*)d_in[7];
    float* out = (float*)d_out;

    rnn_persistent_kernel<<<BB / 2, NTHREADS>>>(y0, u_seq, noise, W_in_raw, W_rec,
                                                b_rec, w_out, b_out, out);
}

// round 4
// speedup vs baseline: 1.4240x; 1.4240x over previous
#include <cuda_runtime.h>
#include <math.h>

// Problem constants
#define BB 256
#define TT 1000
#define NN 200
#define NII 7
#define NT 448              // 14 warps; 224 lane pairs (200 neurons + z + 23 dummy)
#define KREG 80             // floats of W-half kept in registers (40 x b64)
#define KSM  20             // floats of W-half read from SMEM each step (5 x float4)

#define ALPHA_F 0.2f
#define OMA_F   0.8f
#define NSC_F   0.0948683292f   // 0.15*sqrt(2*0.2)

// packed fp32x2 FMA with register-packed W: acc += {wlo,whi}*{ylo,yhi}
__device__ __forceinline__ void ffma2(unsigned long long& acc, unsigned long long w,
                                      float ylo, float yhi) {
    asm("{\n\t"
        ".reg .b64 yy;\n\t"
        "mov.b64 yy, {%2, %3};\n\t"
        "fma.rn.f32x2 %0, %1, yy, %0;\n\t"
        "}"
        : "+l"(acc) : "l"(w), "f"(ylo), "f"(yhi));
}

// packed fp32x2 FMA with scalar-float W operands (W streamed from SMEM)
__device__ __forceinline__ void ffma2f(unsigned long long& acc, float wlo, float whi,
                                       float ylo, float yhi) {
    asm("{\n\t"
        ".reg .b64 ww, yy;\n\t"
        "mov.b64 ww, {%1, %2};\n\t"
        "mov.b64 yy, {%3, %4};\n\t"
        "fma.rn.f32x2 %0, ww, yy, %0;\n\t"
        "}"
        : "+l"(acc) : "f"(wlo), "f"(whi), "f"(ylo), "f"(yhi));
}

__device__ __forceinline__ float hsum2(unsigned long long a) {
    float2 f;
    asm("mov.b64 {%0, %1}, %2;" : "=f"(f.x), "=f"(f.y) : "l"(a));
    return f.x + f.y;
}

// SMEM W-tail layout: two half-arrays; h1 offset tuned so an 8-lane phase
// (lanes = 4 pairs x 2 halves) hits 8 distinct bank quads.
#define WS_HALF_STRIDE 5            // float4 per row
#define WS_H_OFF (201 * WS_HALF_STRIDE + 23)  // pad so h1 base = h0 base + 64B (mod 512B)
#define WS_TOTAL (WS_H_OFF + 201 * WS_HALF_STRIDE)

__global__ void __launch_bounds__(NT, 1)
rnn_persistent_kernel(const float* __restrict__ y0,
                      const float* __restrict__ u_seq,
                      const float* __restrict__ noise,
                      const float* __restrict__ W_in_raw,
                      const float* __restrict__ W_rec,
                      const float* __restrict__ b_rec,
                      const float* __restrict__ w_out,
                      const float* __restrict__ b_out,
                      float* __restrict__ out)
{
    __shared__ __align__(16) float y_s[2][2][NN];   // [buf][row][neuron]
    __shared__ __align__(16) float4 Wsm[WS_TOTAL];  // W tails, [h][row][5]
    __shared__ float wia_s[NN * 9];                 // |W_in| stride 9 (conflict-free)
    __shared__ float u_s[2][2][NII];

    const int tid = threadIdx.x;
    const int h   = tid & 1;           // K-half within lane pair
    const int n   = tid >> 1;          // 0..223
    const int nc  = (n < NN) ? n : NN; // clamp: extras alias w_out row
    const bool is_neuron = (n <  NN);
    const bool is_z      = (n == NN);
    const bool h0        = (h == 0);
    const int  b0 = blockIdx.x * 2;
    const int  b1 = b0 + 1;
    const int  koff = h * 100;

    float* __restrict__ y_seq = out;
    float* __restrict__ z_seq = out + (size_t)BB * TT * NN;
    float* __restrict__ y_fin = out + (size_t)BB * TT * NN + (size_t)BB * TT;

    // ---- W half-row: first 80 floats -> registers, last 20 -> SMEM ----
    unsigned long long w[KREG / 2];
    float4* wtail = &Wsm[h * WS_H_OFF + nc * WS_HALF_STRIDE];
    {
        const float* base = (nc == NN) ? (w_out + koff)
                                       : (W_rec + (size_t)nc * NN + koff);
        const unsigned long long* wp = reinterpret_cast<const unsigned long long*>(base);
        #pragma unroll
        for (int m = 0; m < KREG / 2; ++m) w[m] = __ldg(&wp[m]);
        const float4* wt = reinterpret_cast<const float4*>(base + KREG);
        #pragma unroll
        for (int j = 0; j < KSM / 4; ++j) wtail[j] = __ldg(&wt[j]);
    }
    // |W_in| -> SMEM (cooperative)
    for (int idx = tid; idx < NN * NII; idx += NT) {
        int nn = idx / NII, i = idx % NII;
        wia_s[nn * 9 + i] = fabsf(W_in_raw[idx]);
    }

    float brec = 0.f, bout = 0.f;
    float yold0 = 0.f, yold1 = 0.f, nz0 = 0.f, nz1 = 0.f;
    if (h0 && is_neuron) {
        brec  = b_rec[n];
        yold0 = y0[(size_t)b0 * NN + n];
        yold1 = y0[(size_t)b1 * NN + n];
        y_s[0][0][n] = yold0;
        y_s[0][1][n] = yold1;
        nz0 = noise[(size_t)b0 * TT * NN + n];
        nz1 = noise[(size_t)b1 * TT * NN + n];
    }
    if (is_z) bout = b_out[0];
    if (tid < 2 * NII) {
        int bl = tid / NII, i = tid % NII;
        u_s[0][bl][i] = u_seq[(size_t)(b0 + bl) * TT * NII + i];
    }
    __syncthreads();

    int buf = 0;
    for (int t = 0; t < TT; ++t) {
        // ---- prefetch next step's noise / u ----
        float nz0n = 0.f, nz1n = 0.f, un = 0.f;
        if (h0 && is_neuron && (t + 1 < TT)) {
            nz0n = __ldcs(&noise[((size_t)b0 * TT + (t + 1)) * NN + n]);
            nz1n = __ldcs(&noise[((size_t)b1 * TT + (t + 1)) * NN + n]);
        }
        if (tid < 2 * NII && (t + 1 < TT)) {
            int bl = tid / NII, i = tid % NII;
            un = __ldcs(&u_seq[((size_t)(b0 + bl) * TT + (t + 1)) * NII + i]);
        }

        // ---- half-dot: k in [koff, koff+100) ----
        const float4* Y0 = reinterpret_cast<const float4*>(y_s[buf][0] + koff);
        const float4* Y1 = reinterpret_cast<const float4*>(y_s[buf][1] + koff);
        unsigned long long c0a = 0ull, c0b = 0ull, c1a = 0ull, c1b = 0ull;
        // register part: first 80 k
        #pragma unroll
        for (int m = 0; m < KREG / 8; ++m) {        // 10 iters x 8 floats
            float4 p0 = Y0[2 * m],     p1 = Y0[2 * m + 1];
            float4 q0 = Y1[2 * m],     q1 = Y1[2 * m + 1];
            ffma2(c0a, w[4 * m],     p0.x, p0.y);
            ffma2(c0b, w[4 * m + 1], p0.z, p0.w);
            ffma2(c1a, w[4 * m],     q0.x, q0.y);
            ffma2(c1b, w[4 * m + 1], q0.z, q0.w);
            ffma2(c0a, w[4 * m + 2], p1.x, p1.y);
            ffma2(c0b, w[4 * m + 3], p1.z, p1.w);
            ffma2(c1a, w[4 * m + 2], q1.x, q1.y);
            ffma2(c1b, w[4 * m + 3], q1.z, q1.w);
        }
        // SMEM part: last 20 k
        #pragma unroll
        for (int j = 0; j < KSM / 4; ++j) {
            float4 wf = wtail[j];
            float4 p = Y0[KREG / 4 + j];
            float4 q = Y1[KREG / 4 + j];
            ffma2f(c0a, wf.x, wf.y, p.x, p.y);
            ffma2f(c0b, wf.z, wf.w, p.z, p.w);
            ffma2f(c1a, wf.x, wf.y, q.x, q.y);
            ffma2f(c1b, wf.z, wf.w, q.z, q.w);
        }
        float pre0 = hsum2(c0a) + hsum2(c0b);
        float pre1 = hsum2(c1a) + hsum2(c1b);
        pre0 += __shfl_xor_sync(0xFFFFFFFFu, pre0, 1);
        pre1 += __shfl_xor_sync(0xFFFFFFFFu, pre1, 1);

        if (h0 && is_neuron) {
            float dr0 = brec, dr1 = brec;
            #pragma unroll
            for (int i = 0; i < NII; ++i) {
                float wv = wia_s[n * 9 + i];
                dr0 = fmaf(wv, u_s[buf][0][i], dr0);
                dr1 = fmaf(wv, u_s[buf][1][i], dr1);
            }
            float r0 = fmaxf(pre0 + dr0, 0.f);
            float r1 = fmaxf(pre1 + dr1, 0.f);
            float yn0 = fmaf(OMA_F, yold0, fmaf(ALPHA_F, r0, NSC_F * nz0));
            float yn1 = fmaf(OMA_F, yold1, fmaf(ALPHA_F, r1, NSC_F * nz1));
            y_s[buf ^ 1][0][n] = yn0;
            y_s[buf ^ 1][1][n] = yn1;
            __stcs(&y_seq[((size_t)b0 * TT + t) * NN + n], yn0);
            __stcs(&y_seq[((size_t)b1 * TT + t) * NN + n], yn1);
            yold0 = yn0; yold1 = yn1;
            nz0 = nz0n; nz1 = nz1n;
        } else if (h0 && is_z && t >= 1) {
            z_seq[(size_t)b0 * TT + (t - 1)] = 1.f / (1.f + expf(-(pre0 + bout)));
            z_seq[(size_t)b1 * TT + (t - 1)] = 1.f / (1.f + expf(-(pre1 + bout)));
        }
        if (tid < 2 * NII && (t + 1 < TT)) {
            int bl = tid / NII, i = tid % NII;
            u_s[buf ^ 1][bl][i] = un;
        }
        __syncthreads();
        buf ^= 1;
    }

    // ---- tails ----
    if (h0 && is_neuron) {
        y_fin[(size_t)b0 * NN + n] = yold0;
        y_fin[(size_t)b1 * NN + n] = yold1;
    }
    // final z over y_{T-1} (in y_s[buf]); whole warp executes (shfl safety)
    {
        const float4* Y0 = reinterpret_cast<const float4*>(y_s[buf][0] + koff);
        const float4* Y1 = reinterpret_cast<const float4*>(y_s[buf][1] + koff);
        unsigned long long c0a = 0ull, c0b = 0ull, c1a = 0ull, c1b = 0ull;
        #pragma unroll
        for (int m = 0; m < KREG / 4; ++m) {
            float4 p = Y0[m];
            float4 q = Y1[m];
            ffma2(c0a, w[2 * m],     p.x, p.y);
            ffma2(c0b, w[2 * m + 1], p.z, p.w);
            ffma2(c1a, w[2 * m],     q.x, q.y);
            ffma2(c1b, w[2 * m + 1], q.z, q.w);
        }
        #pragma unroll
        for (int j = 0; j < KSM / 4; ++j) {
            float4 wf = wtail[j];
            float4 p = Y0[KREG / 4 + j];
            float4 q = Y1[KREG / 4 + j];
            ffma2f(c0a, wf.x, wf.y, p.x, p.y);
            ffma2f(c0b, wf.z, wf.w, p.z, p.w);
            ffma2f(c1a, wf.x, wf.y, q.x, q.y);
            ffma2f(c1b, wf.z, wf.w, q.z, q.w);
        }
        float pre0 = hsum2(c0a) + hsum2(c0b);
        float pre1 = hsum2(c1a) + hsum2(c1b);
        pre0 += __shfl_xor_sync(0xFFFFFFFFu, pre0, 1);
        pre1 += __shfl_xor_sync(0xFFFFFFFFu, pre1, 1);
        if (h0 && is_z) {
            z_seq[(size_t)b0 * TT + (TT - 1)] = 1.f / (1.f + expf(-(pre0 + bout)));
            z_seq[(size_t)b1 * TT + (TT - 1)] = 1.f / (1.f + expf(-(pre1 + bout)));
        }
    }
}

extern "C" void kernel_launch(void* const* d_in, const int* in_sizes, int n_in,
                              void* d_out, int out_size) {
    const float* y0       = (const float*)d_in[0];
    const float* u_seq    = (const float*)d_in[1];
    const float* noise    = (const float*)d_in[2];
    const float* W_in_raw = (const float*)d_in[3];
    const float* W_rec    = (const float*)d_in[4];
    const float* b_rec    = (const float*)d_in[5];
    const float* w_out    = (const float*)d_in[6];
    const float* b_out    = (const float*)d_in[7];
    float* out = (float*)d_out;

    rnn_persistent_kernel<<<BB / 2, NT>>>(y0, u_seq, noise, W_in_raw, W_rec,
                                          b_rec, w_out, b_out, out);
}

// round 5
// speedup vs baseline: 1.6638x; 1.1684x over previous
#include <cuda_runtime.h>
#include <math.h>

// Problem constants
#define BB 256
#define TT 1000
#define NN 200
#define NII 7
#define KR 160              // W floats kept in registers (80 x b64)
#define KT 40               // W tail floats read from SMEM (10 x float4)
#define TS 11               // tail stride in float4 (odd -> conflict-free)

#define ALPHA_F 0.2f
#define OMA_F   0.8f
#define NSC_F   0.0948683292f   // 0.15*sqrt(2*0.2)

// packed fp32x2 FMA, W packed in b64
__device__ __forceinline__ void ffma2(unsigned long long& acc, unsigned long long w,
                                      float ylo, float yhi) {
    asm("{\n\t"
        ".reg .b64 yy;\n\t"
        "mov.b64 yy, {%2, %3};\n\t"
        "fma.rn.f32x2 %0, %1, yy, %0;\n\t"
        "}"
        : "+l"(acc) : "l"(w), "f"(ylo), "f"(yhi));
}

// packed fp32x2 FMA, W as two scalar floats (streamed from SMEM)
__device__ __forceinline__ void ffma2f(unsigned long long& acc, float wlo, float whi,
                                       float ylo, float yhi) {
    asm("{\n\t"
        ".reg .b64 ww, yy;\n\t"
        "mov.b64 ww, {%1, %2};\n\t"
        "mov.b64 yy, {%3, %4};\n\t"
        "fma.rn.f32x2 %0, ww, yy, %0;\n\t"
        "}"
        : "+l"(acc) : "f"(wlo), "f"(whi), "f"(ylo), "f"(yhi));
}

__device__ __forceinline__ float hsum2(unsigned long long a) {
    float2 f;
    asm("mov.b64 {%0, %1}, %2;" : "=f"(f.x), "=f"(f.y) : "l"(a));
    return f.x + f.y;
}

__global__ void __launch_bounds__(256, 1)
rnn_persistent_kernel(const float* __restrict__ y0,
                      const float* __restrict__ u_seq,
                      const float* __restrict__ noise,
                      const float* __restrict__ W_in_raw,
                      const float* __restrict__ W_rec,
                      const float* __restrict__ b_rec,
                      const float* __restrict__ w_out,
                      const float* __restrict__ b_out,
                      float* __restrict__ out)
{
    __shared__ __align__(16) float y_s[2][2][NN];     // [buf][row][neuron]
    __shared__ __align__(16) float4 Wt_s[201 * TS];   // W tails, [row][10 of 11]
    __shared__ float wia_s[NN * 9];                   // |W_in| stride 9
    __shared__ float u_s[2][2][NII];

    const int tid = threadIdx.x;
    const int n   = tid;                 // neuron id; 200 = z; 201..255 idle
    const bool is_neuron = (n <  NN);
    const bool is_z      = (n == NN);
    const bool active    = (n <= NN);
    const int  b0 = blockIdx.x * 2;
    const int  b1 = b0 + 1;

    float* __restrict__ y_seq = out;
    float* __restrict__ z_seq = out + (size_t)BB * TT * NN;
    float* __restrict__ y_fin = out + (size_t)BB * TT * NN + (size_t)BB * TT;

    // ---- W row: first 160 floats -> registers, last 40 -> SMEM tail ----
    unsigned long long w[KR / 2];
    const float4* wtail = &Wt_s[(active ? n : NN) * TS];
    if (active) {
        const float* base = is_z ? w_out : (W_rec + (size_t)n * NN);
        const unsigned long long* wp = reinterpret_cast<const unsigned long long*>(base);
        #pragma unroll
        for (int m = 0; m < KR / 2; ++m) w[m] = __ldg(&wp[m]);
        const float4* wt = reinterpret_cast<const float4*>(base + KR);
        float4* dst = &Wt_s[n * TS];
        #pragma unroll
        for (int j = 0; j < KT / 4; ++j) dst[j] = __ldg(&wt[j]);
    }
    // |W_in| -> SMEM
    for (int idx = tid; idx < NN * NII; idx += 256) {
        int nn = idx / NII, i = idx % NII;
        wia_s[nn * 9 + i] = fabsf(W_in_raw[idx]);
    }

    float brec = 0.f, bout = 0.f;
    float yold0 = 0.f, yold1 = 0.f, nz0 = 0.f, nz1 = 0.f;
    if (is_neuron) {
        brec  = b_rec[n];
        yold0 = y0[(size_t)b0 * NN + n];
        yold1 = y0[(size_t)b1 * NN + n];
        y_s[0][0][n] = yold0;
        y_s[0][1][n] = yold1;
        nz0 = noise[(size_t)b0 * TT * NN + n];
        nz1 = noise[(size_t)b1 * TT * NN + n];
    }
    if (is_z) bout = b_out[0];
    if (tid < 2 * NII) {
        int bl = tid / NII, i = tid % NII;
        u_s[0][bl][i] = u_seq[(size_t)(b0 + bl) * TT * NII + i];
    }
    __syncthreads();

    int buf = 0;
    for (int t = 0; t < TT; ++t) {
        // ---- prefetch next step's noise / u ----
        float nz0n = 0.f, nz1n = 0.f, un = 0.f;
        if (is_neuron && (t + 1 < TT)) {
            nz0n = __ldcs(&noise[((size_t)b0 * TT + (t + 1)) * NN + n]);
            nz1n = __ldcs(&noise[((size_t)b1 * TT + (t + 1)) * NN + n]);
        }
        if (tid < 2 * NII && (t + 1 < TT)) {
            int bl = tid / NII, i = tid % NII;
            un = __ldcs(&u_seq[((size_t)(b0 + bl) * TT + (t + 1)) * NII + i]);
        }

        if (active) {
            const float4* Y0 = reinterpret_cast<const float4*>(y_s[buf][0]);
            const float4* Y1 = reinterpret_cast<const float4*>(y_s[buf][1]);
            unsigned long long c0a = 0ull, c0b = 0ull, c1a = 0ull, c1b = 0ull;
            // register part: k in [0,160)
            #pragma unroll
            for (int m = 0; m < KR / 8; ++m) {           // 20 iters x 8 floats
                float4 p0 = Y0[2 * m], p1 = Y0[2 * m + 1];
                float4 q0 = Y1[2 * m], q1 = Y1[2 * m + 1];
                ffma2(c0a, w[4 * m + 0], p0.x, p0.y);
                ffma2(c0b, w[4 * m + 1], p0.z, p0.w);
                ffma2(c1a, w[4 * m + 0], q0.x, q0.y);
                ffma2(c1b, w[4 * m + 1], q0.z, q0.w);
                ffma2(c0a, w[4 * m + 2], p1.x, p1.y);
                ffma2(c0b, w[4 * m + 3], p1.z, p1.w);
                ffma2(c1a, w[4 * m + 2], q1.x, q1.y);
                ffma2(c1b, w[4 * m + 3], q1.z, q1.w);
            }
            // SMEM tail: k in [160,200)
            #pragma unroll
            for (int j = 0; j < KT / 4; ++j) {
                float4 wf = wtail[j];
                float4 p = Y0[KR / 4 + j];
                float4 q = Y1[KR / 4 + j];
                ffma2f(c0a, wf.x, wf.y, p.x, p.y);
                ffma2f(c0b, wf.z, wf.w, p.z, p.w);
                ffma2f(c1a, wf.x, wf.y, q.x, q.y);
                ffma2f(c1b, wf.z, wf.w, q.z, q.w);
            }
            float pre0 = hsum2(c0a) + hsum2(c0b);
            float pre1 = hsum2(c1a) + hsum2(c1b);

            if (is_neuron) {
                float dr0 = brec, dr1 = brec;
                #pragma unroll
                for (int i = 0; i < NII; ++i) {
                    float wv = wia_s[n * 9 + i];
                    dr0 = fmaf(wv, u_s[buf][0][i], dr0);
                    dr1 = fmaf(wv, u_s[buf][1][i], dr1);
                }
                float r0 = fmaxf(pre0 + dr0, 0.f);
                float r1 = fmaxf(pre1 + dr1, 0.f);
                float yn0 = fmaf(OMA_F, yold0, fmaf(ALPHA_F, r0, NSC_F * nz0));
                float yn1 = fmaf(OMA_F, yold1, fmaf(ALPHA_F, r1, NSC_F * nz1));
                y_s[buf ^ 1][0][n] = yn0;
                y_s[buf ^ 1][1][n] = yn1;
                __stcs(&y_seq[((size_t)b0 * TT + t) * NN + n], yn0);
                __stcs(&y_seq[((size_t)b1 * TT + t) * NN + n], yn1);
                yold0 = yn0; yold1 = yn1;
                nz0 = nz0n; nz1 = nz1n;
            } else if (t >= 1) {
                // z thread's dot was over y_{t-1}
                z_seq[(size_t)b0 * TT + (t - 1)] = 1.f / (1.f + expf(-(pre0 + bout)));
                z_seq[(size_t)b1 * TT + (t - 1)] = 1.f / (1.f + expf(-(pre1 + bout)));
            }
        }
        if (tid < 2 * NII && (t + 1 < TT)) {
            int bl = tid / NII, i = tid % NII;
            u_s[buf ^ 1][bl][i] = un;
        }
        __syncthreads();
        buf ^= 1;
    }

    // ---- tails ----
    if (is_neuron) {
        y_fin[(size_t)b0 * NN + n] = yold0;
        y_fin[(size_t)b1 * NN + n] = yold1;
    }
    if (is_z) {
        const float4* Y0 = reinterpret_cast<const float4*>(y_s[buf][0]);
        const float4* Y1 = reinterpret_cast<const float4*>(y_s[buf][1]);
        unsigned long long c0a = 0ull, c0b = 0ull, c1a = 0ull, c1b = 0ull;
        #pragma unroll
        for (int m = 0; m < KR / 4; ++m) {
            float4 p = Y0[m];
            float4 q = Y1[m];
            ffma2(c0a, w[2 * m],     p.x, p.y);
            ffma2(c0b, w[2 * m + 1], p.z, p.w);
            ffma2(c1a, w[2 * m],     q.x, q.y);
            ffma2(c1b, w[2 * m + 1], q.z, q.w);
        }
        #pragma unroll
        for (int j = 0; j < KT / 4; ++j) {
            float4 wf = wtail[j];
            float4 p = Y0[KR / 4 + j];
            float4 q = Y1[KR / 4 + j];
            ffma2f(c0a, wf.x, wf.y, p.x, p.y);
            ffma2f(c0b, wf.z, wf.w, p.z, p.w);
            ffma2f(c1a, wf.x, wf.y, q.x, q.y);
            ffma2f(c1b, wf.z, wf.w, q.z, q.w);
        }
        float pre0 = hsum2(c0a) + hsum2(c0b);
        float pre1 = hsum2(c1a) + hsum2(c1b);
        z_seq[(size_t)b0 * TT + (TT - 1)] = 1.f / (1.f + expf(-(pre0 + bout)));
        z_seq[(size_t)b1 * TT + (TT - 1)] = 1.f / (1.f + expf(-(pre1 + bout)));
    }
}

extern "C" void kernel_launch(void* const* d_in, const int* in_sizes, int n_in,
                              void* d_out, int out_size) {
    const float* y0       = (const float*)d_in[0];
    const float* u_seq    = (const float*)d_in[1];
    const float* noise    = (const float*)d_in[2];
    const float* W_in_raw = (const float*)d_in[3];
    const float* W_rec    = (const float*)d_in[4];
    const float* b_rec    = (const float*)d_in[5];
    const float* w_out    = (const float*)d_in[6];
    const float* b_out    = (const float*)d_in[7];
    float* out = (float*)d_out;

    rnn_persistent_kernel<<<BB / 2, 256>>>(y0, u_seq, noise, W_in_raw, W_rec,
                                           b_rec, w_out, b_out, out);
}